// round 6
// baseline (speedup 1.0000x reference)
#include <cuda_runtime.h>
#include <cuda_bf16.h>

// Per-species linear (X[n,64] . W[species[n],64,1]) + segment_sum over sorted
// structural_indices -> out[n_structures].
// R5: single-wave persistent grid (148 SMs x 3 CTAs = 444 blocks, all
// resident) to kill wave quantization (R4 ran 2.67 waves -> 89% util cap).
// Mainloop unchanged from R4: 16-atom warp batches, 8 front-batched __ldcs
// float4 loads per lane, sorted-run fast path, boundary-only shuffles+atomics.

#define WARPS_PER_BLOCK 8
#define THREADS_PER_BLOCK (WARPS_PER_BLOCK * 32)
#define CTAS_PER_SM 3
#define NUM_SMS 148
#define N_SPECIES 8
#define D_VEC4 16   // 64 floats / 4

__global__ __launch_bounds__(THREADS_PER_BLOCK, CTAS_PER_SM)
void atomistic_kernel(const float4* __restrict__ X4,
                      const float*  __restrict__ W,
                      const int*    __restrict__ species,
                      const int*    __restrict__ struct_idx,
                      float*        __restrict__ out,
                      int n_atoms,
                      int atoms_per_warp)   // multiple of 8
{
    __shared__ float4 Wsh[N_SPECIES * D_VEC4];
    for (int i = threadIdx.x; i < N_SPECIES * D_VEC4; i += blockDim.x)
        Wsh[i] = reinterpret_cast<const float4*>(W)[i];
    __syncthreads();

    const int warp = blockIdx.x * WARPS_PER_BLOCK + (threadIdx.x >> 5);
    const int lane = threadIdx.x & 31;
    const int half = lane >> 4;                  // which 8-atom group of the batch
    const int sub  = lane & 15;                  // float4 column within the row
    const unsigned halfmask = 0xFFFFu << (half * 16);

    long long start = (long long)warp * atoms_per_warp;
    long long end   = start + atoms_per_warp;
    if (end > n_atoms) end = (long long)n_atoms;
    if (start >= end) return;                    // uniform per warp

    const long long n      = end - start;
    const long long nbatch = n >> 4;             // batches of 16 atoms

    int   cur_key = -1;
    float acc0 = 0.0f, acc1 = 0.0f, acc2 = 0.0f, acc3 = 0.0f;

    // Flush the current segment for this half-warp (call half-converged).
    auto flush = [&]() {
        float t = (acc0 + acc1) + (acc2 + acc3);
        t += __shfl_xor_sync(halfmask, t, 8);
        t += __shfl_xor_sync(halfmask, t, 4);
        t += __shfl_xor_sync(halfmask, t, 2);
        t += __shfl_xor_sync(halfmask, t, 1);
        if (sub == 0 && cur_key >= 0)
            atomicAdd(out + cur_key, t);
    };
    // Process one atom with boundary check (slow path / tail).
    auto proc1 = [&](int k, int s, float4 x) {
        if (k != cur_key) {
            flush();
            cur_key = k; acc0 = acc1 = acc2 = acc3 = 0.0f;
        }
        const float4 w = Wsh[s * D_VEC4 + sub];
        acc0 = fmaf(x.x, w.x, acc0);
        acc1 = fmaf(x.y, w.y, acc1);
        acc2 = fmaf(x.z, w.z, acc2);
        acc3 = fmaf(x.w, w.w, acc3);
    };
    // One fully-loaded atom on the fast path.
    auto fma4 = [&](int s, const float4& x) {
        const float4 w = Wsh[s * D_VEC4 + sub];
        acc0 = fmaf(x.x, w.x, acc0);
        acc1 = fmaf(x.y, w.y, acc1);
        acc2 = fmaf(x.z, w.z, acc2);
        acc3 = fmaf(x.w, w.w, acc3);
    };

    // Hot-loop pointers (this half's first atom is start + half*8).
    const long long a0 = start + half * 8;
    const float4* xp = X4 + a0 * D_VEC4 + sub;
    const int*    kp = struct_idx + a0;
    const int*    sp = species + a0;

    for (long long b = 0; b < nbatch; ++b) {
        // Front-batched loads: 8 independent streaming float4s + vector keys.
        const float4 x0 = __ldcs(xp);
        const float4 x1 = __ldcs(xp + 1 * D_VEC4);
        const float4 x2 = __ldcs(xp + 2 * D_VEC4);
        const float4 x3 = __ldcs(xp + 3 * D_VEC4);
        const float4 x4 = __ldcs(xp + 4 * D_VEC4);
        const float4 x5 = __ldcs(xp + 5 * D_VEC4);
        const float4 x6 = __ldcs(xp + 6 * D_VEC4);
        const float4 x7 = __ldcs(xp + 7 * D_VEC4);
        const int4 kv0 = *reinterpret_cast<const int4*>(kp);
        const int4 kv1 = *reinterpret_cast<const int4*>(kp + 4);
        const int4 sv0 = *reinterpret_cast<const int4*>(sp);
        const int4 sv1 = *reinterpret_cast<const int4*>(sp + 4);
        xp += 16 * D_VEC4;   // 16 atoms forward (both halves)
        kp += 16;
        sp += 16;

        if (kv0.x == cur_key && kv1.w == cur_key) {
            // Sorted keys + first==last==cur -> all 8 atoms in current segment.
            fma4(sv0.x, x0); fma4(sv0.y, x1); fma4(sv0.z, x2); fma4(sv0.w, x3);
            fma4(sv1.x, x4); fma4(sv1.y, x5); fma4(sv1.z, x6); fma4(sv1.w, x7);
        } else {
            proc1(kv0.x, sv0.x, x0);
            proc1(kv0.y, sv0.y, x1);
            proc1(kv0.z, sv0.z, x2);
            proc1(kv0.w, sv0.w, x3);
            proc1(kv1.x, sv1.x, x4);
            proc1(kv1.y, sv1.y, x5);
            proc1(kv1.z, sv1.z, x6);
            proc1(kv1.w, sv1.w, x7);
        }
    }

    // Tail (< 16 atoms): 2 atoms per step, halves interleave; keys stay
    // monotone per half.
    for (long long a = start + nbatch * 16 + half; a < end; a += 2) {
        const int k = struct_idx[a];
        const int s = species[a];
        const float4 x = __ldcs(&X4[a * D_VEC4 + sub]);
        proc1(k, s, x);
    }

    // Final flush (all lanes converged here).
    flush();
}

extern "C" void kernel_launch(void* const* d_in, const int* in_sizes, int n_in,
                              void* d_out, int out_size)
{
    // Input order: X, W, central_species, structural_indices, n_structures
    const float* X  = (const float*)d_in[0];
    const float* W  = (const float*)d_in[1];
    const int*   sp = (const int*)  d_in[2];
    const int*   si = (const int*)  d_in[3];
    float* out = (float*)d_out;

    const int n_atoms = in_sizes[2];

    cudaMemsetAsync(d_out, 0, (size_t)out_size * sizeof(float), 0);

    // Single wave: every CTA resident simultaneously (148 SMs x 3 CTAs/SM).
    const int blocks = NUM_SMS * CTAS_PER_SM;   // 444
    const int total_warps = blocks * WARPS_PER_BLOCK;
    // apw multiple of 8 keeps the int4 key/species loads 16B-aligned
    // (start % 8 == 0 -> start + half*8 is 4-int aligned).
    int apw = (n_atoms + total_warps - 1) / total_warps;
    apw = (apw + 7) & ~7;

    atomistic_kernel<<<blocks, THREADS_PER_BLOCK>>>(
        (const float4*)X, W, sp, si, out, n_atoms, apw);
}

// round 7
// speedup vs baseline: 1.0114x; 1.0114x over previous
#include <cuda_runtime.h>
#include <cuda_bf16.h>

// Per-species linear (X[n,64] . W[species[n],64,1]) + segment_sum over sorted
// structural_indices -> out[n_structures].
// R6: evidence from R4/R5 says we're pinned at the achievable HBM streaming
// ceiling (~6.4 TB/s) regardless of occupancy/grid. This round combines the
// three proven-good properties in one config: 8-atom batch mainloop (48 regs),
// single-wave grid at 5 CTAs/SM (148*5 = 740 blocks, 40 warps/SM resident),
// short per-warp chunks (~344 atoms) to minimize straggler spread.

#define WARPS_PER_BLOCK 8
#define THREADS_PER_BLOCK (WARPS_PER_BLOCK * 32)
#define CTAS_PER_SM 5
#define NUM_SMS 148
#define N_SPECIES 8
#define D_VEC4 16   // 64 floats / 4

__global__ __launch_bounds__(THREADS_PER_BLOCK, CTAS_PER_SM)
void atomistic_kernel(const float4* __restrict__ X4,
                      const float*  __restrict__ W,
                      const int*    __restrict__ species,
                      const int*    __restrict__ struct_idx,
                      float*        __restrict__ out,
                      int n_atoms,
                      int atoms_per_warp)   // multiple of 8
{
    __shared__ float4 Wsh[N_SPECIES * D_VEC4];
    for (int i = threadIdx.x; i < N_SPECIES * D_VEC4; i += blockDim.x)
        Wsh[i] = reinterpret_cast<const float4*>(W)[i];
    __syncthreads();

    const int warp = blockIdx.x * WARPS_PER_BLOCK + (threadIdx.x >> 5);
    const int lane = threadIdx.x & 31;
    const int half = lane >> 4;                  // which 4-atom group of the batch
    const int sub  = lane & 15;                  // float4 column within the row
    const unsigned halfmask = 0xFFFFu << (half * 16);

    long long start = (long long)warp * atoms_per_warp;
    long long end   = start + atoms_per_warp;
    if (end > n_atoms) end = (long long)n_atoms;
    if (start >= end) return;                    // uniform per warp

    const long long n      = end - start;
    const long long nbatch = n >> 3;             // batches of 8 atoms

    int   cur_key = -1;
    float acc0 = 0.0f, acc1 = 0.0f;

    // Flush the current segment for this half-warp (call half-converged).
    auto flush = [&]() {
        float t = acc0 + acc1;
        t += __shfl_xor_sync(halfmask, t, 8);
        t += __shfl_xor_sync(halfmask, t, 4);
        t += __shfl_xor_sync(halfmask, t, 2);
        t += __shfl_xor_sync(halfmask, t, 1);
        if (sub == 0 && cur_key >= 0)
            atomicAdd(out + cur_key, t);
    };
    // Process one atom with boundary check (slow path / tail).
    auto proc1 = [&](int k, int s, float4 x) {
        if (k != cur_key) {
            flush();
            cur_key = k; acc0 = 0.0f; acc1 = 0.0f;
        }
        const float4 w = Wsh[s * D_VEC4 + sub];
        acc0 = fmaf(x.x, w.x, acc0);
        acc1 = fmaf(x.y, w.y, acc1);
        acc0 = fmaf(x.z, w.z, acc0);
        acc1 = fmaf(x.w, w.w, acc1);
    };
    // One fully-loaded atom on the fast path.
    auto fma4 = [&](int s, const float4& x) {
        const float4 w = Wsh[s * D_VEC4 + sub];
        acc0 = fmaf(x.x, w.x, acc0);
        acc1 = fmaf(x.y, w.y, acc1);
        acc0 = fmaf(x.z, w.z, acc0);
        acc1 = fmaf(x.w, w.w, acc1);
    };

    // Hot-loop pointers (this half's first atom is start + half*4).
    const long long a0 = start + half * 4;
    const float4* xp = X4 + a0 * D_VEC4 + sub;
    const int*    kp = struct_idx + a0;
    const int*    sp = species + a0;

    for (long long b = 0; b < nbatch; ++b) {
        // Front-batched loads: 4 independent streaming float4s + vector keys.
        const float4 x0 = __ldcs(xp);
        const float4 x1 = __ldcs(xp + 1 * D_VEC4);
        const float4 x2 = __ldcs(xp + 2 * D_VEC4);
        const float4 x3 = __ldcs(xp + 3 * D_VEC4);
        const int4 kv = *reinterpret_cast<const int4*>(kp);
        const int4 sv = *reinterpret_cast<const int4*>(sp);
        xp += 8 * D_VEC4;   // 8 atoms forward (both halves)
        kp += 8;
        sp += 8;

        if (kv.x == cur_key && kv.w == cur_key) {
            // Sorted keys + first==last==cur -> all 4 atoms in current segment.
            fma4(sv.x, x0); fma4(sv.y, x1); fma4(sv.z, x2); fma4(sv.w, x3);
        } else {
            proc1(kv.x, sv.x, x0);
            proc1(kv.y, sv.y, x1);
            proc1(kv.z, sv.z, x2);
            proc1(kv.w, sv.w, x3);
        }
    }

    // Tail (< 8 atoms): 2 atoms per step, halves interleave; keys stay
    // monotone per half.
    for (long long a = start + nbatch * 8 + half; a < end; a += 2) {
        const int k = struct_idx[a];
        const int s = species[a];
        const float4 x = __ldcs(&X4[a * D_VEC4 + sub]);
        proc1(k, s, x);
    }

    // Final flush (all lanes converged here).
    flush();
}

extern "C" void kernel_launch(void* const* d_in, const int* in_sizes, int n_in,
                              void* d_out, int out_size)
{
    // Input order: X, W, central_species, structural_indices, n_structures
    const float* X  = (const float*)d_in[0];
    const float* W  = (const float*)d_in[1];
    const int*   sp = (const int*)  d_in[2];
    const int*   si = (const int*)  d_in[3];
    float* out = (float*)d_out;

    const int n_atoms = in_sizes[2];

    cudaMemsetAsync(d_out, 0, (size_t)out_size * sizeof(float), 0);

    // Single wave at 5 CTAs/SM (48-reg kernel): 148 * 5 = 740 blocks, all
    // resident simultaneously; 40 warps/SM.
    const int blocks = NUM_SMS * CTAS_PER_SM;   // 740
    const int total_warps = blocks * WARPS_PER_BLOCK;
    // apw multiple of 8 keeps the int4 key/species loads 16B-aligned.
    int apw = (n_atoms + total_warps - 1) / total_warps;
    apw = (apw + 7) & ~7;

    atomistic_kernel<<<blocks, THREADS_PER_BLOCK>>>(
        (const float4*)X, W, sp, si, out, n_atoms, apw);
}

// round 8
// speedup vs baseline: 1.0122x; 1.0008x over previous
#include <cuda_runtime.h>
#include <cuda_bf16.h>

// Per-species linear (X[n,64] . W[species[n],64,1]) + segment_sum over sorted
// structural_indices -> out[n_structures].
// R7: R5 config (empirical optimum: 16-atom batches, 444-block single wave,
// 3 CTAs/SM) + balanced 8-atom-chunk work distribution (no idle warps, no
// over-full warps). We are at the achieved-HBM roofline (~6.4 TB/s, 528 MB
// streamed -> ~80 us floor); this round removes the last ~1% imbalance.

#define WARPS_PER_BLOCK 8
#define THREADS_PER_BLOCK (WARPS_PER_BLOCK * 32)
#define CTAS_PER_SM 3
#define NUM_SMS 148
#define N_SPECIES 8
#define D_VEC4 16   // 64 floats / 4

__global__ __launch_bounds__(THREADS_PER_BLOCK, CTAS_PER_SM)
void atomistic_kernel(const float4* __restrict__ X4,
                      const float*  __restrict__ W,
                      const int*    __restrict__ species,
                      const int*    __restrict__ struct_idx,
                      float*        __restrict__ out,
                      int n_atoms,
                      int chunks_base,   // 8-atom chunks per warp (floor)
                      int chunks_rem)    // first chunks_rem warps get one extra
{
    __shared__ float4 Wsh[N_SPECIES * D_VEC4];
    for (int i = threadIdx.x; i < N_SPECIES * D_VEC4; i += blockDim.x)
        Wsh[i] = reinterpret_cast<const float4*>(W)[i];
    __syncthreads();

    const int warp = blockIdx.x * WARPS_PER_BLOCK + (threadIdx.x >> 5);
    const int lane = threadIdx.x & 31;
    const int half = lane >> 4;                  // which 8-atom group of the batch
    const int sub  = lane & 15;                  // float4 column within the row
    const unsigned halfmask = 0xFFFFu << (half * 16);

    // Balanced distribution in units of 8-atom chunks (keeps 16B alignment
    // of the int4 key/species loads: every start is a multiple of 8 atoms).
    const int  my_chunks  = chunks_base + (warp < chunks_rem);
    const long long start = 8LL * ((long long)warp * chunks_base +
                                   (warp < chunks_rem ? warp : chunks_rem));
    long long end = start + 8LL * my_chunks;
    if (end > n_atoms) end = (long long)n_atoms;
    if (start >= end) return;                    // uniform per warp

    const long long n      = end - start;
    const long long nbatch = n >> 4;             // batches of 16 atoms

    int   cur_key = -1;
    float acc0 = 0.0f, acc1 = 0.0f, acc2 = 0.0f, acc3 = 0.0f;

    // Flush the current segment for this half-warp (call half-converged).
    auto flush = [&]() {
        float t = (acc0 + acc1) + (acc2 + acc3);
        t += __shfl_xor_sync(halfmask, t, 8);
        t += __shfl_xor_sync(halfmask, t, 4);
        t += __shfl_xor_sync(halfmask, t, 2);
        t += __shfl_xor_sync(halfmask, t, 1);
        if (sub == 0 && cur_key >= 0)
            atomicAdd(out + cur_key, t);
    };
    // Process one atom with boundary check (slow path / tail).
    auto proc1 = [&](int k, int s, float4 x) {
        if (k != cur_key) {
            flush();
            cur_key = k; acc0 = acc1 = acc2 = acc3 = 0.0f;
        }
        const float4 w = Wsh[s * D_VEC4 + sub];
        acc0 = fmaf(x.x, w.x, acc0);
        acc1 = fmaf(x.y, w.y, acc1);
        acc2 = fmaf(x.z, w.z, acc2);
        acc3 = fmaf(x.w, w.w, acc3);
    };
    // One fully-loaded atom on the fast path.
    auto fma4 = [&](int s, const float4& x) {
        const float4 w = Wsh[s * D_VEC4 + sub];
        acc0 = fmaf(x.x, w.x, acc0);
        acc1 = fmaf(x.y, w.y, acc1);
        acc2 = fmaf(x.z, w.z, acc2);
        acc3 = fmaf(x.w, w.w, acc3);
    };

    // Hot-loop pointers (this half's first atom is start + half*8).
    const long long a0 = start + half * 8;
    const float4* xp = X4 + a0 * D_VEC4 + sub;
    const int*    kp = struct_idx + a0;
    const int*    sp = species + a0;

    for (long long b = 0; b < nbatch; ++b) {
        // Front-batched loads: 8 independent streaming float4s + vector keys.
        const float4 x0 = __ldcs(xp);
        const float4 x1 = __ldcs(xp + 1 * D_VEC4);
        const float4 x2 = __ldcs(xp + 2 * D_VEC4);
        const float4 x3 = __ldcs(xp + 3 * D_VEC4);
        const float4 x4 = __ldcs(xp + 4 * D_VEC4);
        const float4 x5 = __ldcs(xp + 5 * D_VEC4);
        const float4 x6 = __ldcs(xp + 6 * D_VEC4);
        const float4 x7 = __ldcs(xp + 7 * D_VEC4);
        const int4 kv0 = *reinterpret_cast<const int4*>(kp);
        const int4 kv1 = *reinterpret_cast<const int4*>(kp + 4);
        const int4 sv0 = *reinterpret_cast<const int4*>(sp);
        const int4 sv1 = *reinterpret_cast<const int4*>(sp + 4);
        xp += 16 * D_VEC4;   // 16 atoms forward (both halves)
        kp += 16;
        sp += 16;

        if (kv0.x == cur_key && kv1.w == cur_key) {
            // Sorted keys + first==last==cur -> all 8 atoms in current segment.
            fma4(sv0.x, x0); fma4(sv0.y, x1); fma4(sv0.z, x2); fma4(sv0.w, x3);
            fma4(sv1.x, x4); fma4(sv1.y, x5); fma4(sv1.z, x6); fma4(sv1.w, x7);
        } else {
            proc1(kv0.x, sv0.x, x0);
            proc1(kv0.y, sv0.y, x1);
            proc1(kv0.z, sv0.z, x2);
            proc1(kv0.w, sv0.w, x3);
            proc1(kv1.x, sv1.x, x4);
            proc1(kv1.y, sv1.y, x5);
            proc1(kv1.z, sv1.z, x6);
            proc1(kv1.w, sv1.w, x7);
        }
    }

    // Tail (< 16 atoms): 2 atoms per step, halves interleave; keys stay
    // monotone per half.
    for (long long a = start + nbatch * 16 + half; a < end; a += 2) {
        const int k = struct_idx[a];
        const int s = species[a];
        const float4 x = __ldcs(&X4[a * D_VEC4 + sub]);
        proc1(k, s, x);
    }

    // Final flush (all lanes converged here).
    flush();
}

extern "C" void kernel_launch(void* const* d_in, const int* in_sizes, int n_in,
                              void* d_out, int out_size)
{
    // Input order: X, W, central_species, structural_indices, n_structures
    const float* X  = (const float*)d_in[0];
    const float* W  = (const float*)d_in[1];
    const int*   sp = (const int*)  d_in[2];
    const int*   si = (const int*)  d_in[3];
    float* out = (float*)d_out;

    const int n_atoms = in_sizes[2];

    cudaMemsetAsync(d_out, 0, (size_t)out_size * sizeof(float), 0);

    // Single wave: 148 SMs x 3 CTAs/SM, all resident simultaneously.
    const int blocks = NUM_SMS * CTAS_PER_SM;          // 444
    const int total_warps = blocks * WARPS_PER_BLOCK;  // 3552

    // Balanced distribution of 8-atom chunks across warps.
    const int total_chunks = (n_atoms + 7) >> 3;       // 250000 for 2M atoms
    const int chunks_base  = total_chunks / total_warps;
    const int chunks_rem   = total_chunks % total_warps;

    atomistic_kernel<<<blocks, THREADS_PER_BLOCK>>>(
        (const float4*)X, W, sp, si, out, n_atoms, chunks_base, chunks_rem);
}

// round 9
// speedup vs baseline: 1.0283x; 1.0159x over previous
#include <cuda_runtime.h>
#include <cuda_bf16.h>

// Per-species linear (X[n,64] . W[species[n],64,1]) + segment_sum over sorted
// structural_indices -> out[n_structures].
// R8: evidence across R4-R7 says multi-wave oversubscription beats single-wave
// equal-split (work-smoothing vs straggler spread). This round: the 8-atom
// mainloop (48 regs, 5 CTAs/SM resident, best measured HBM 6434 GB/s) at
// grid 2368 (~3.2 waves, ~106 atoms/warp) with balanced chunk distribution.

#define WARPS_PER_BLOCK 8
#define THREADS_PER_BLOCK (WARPS_PER_BLOCK * 32)
#define N_SPECIES 8
#define D_VEC4 16   // 64 floats / 4

__global__ __launch_bounds__(THREADS_PER_BLOCK)
void atomistic_kernel(const float4* __restrict__ X4,
                      const float*  __restrict__ W,
                      const int*    __restrict__ species,
                      const int*    __restrict__ struct_idx,
                      float*        __restrict__ out,
                      int n_atoms,
                      int chunks_base,   // 8-atom chunks per warp (floor)
                      int chunks_rem)    // first chunks_rem warps get one extra
{
    __shared__ float4 Wsh[N_SPECIES * D_VEC4];
    for (int i = threadIdx.x; i < N_SPECIES * D_VEC4; i += blockDim.x)
        Wsh[i] = reinterpret_cast<const float4*>(W)[i];
    __syncthreads();

    const int warp = blockIdx.x * WARPS_PER_BLOCK + (threadIdx.x >> 5);
    const int lane = threadIdx.x & 31;
    const int half = lane >> 4;                  // which 4-atom group of the batch
    const int sub  = lane & 15;                  // float4 column within the row
    const unsigned halfmask = 0xFFFFu << (half * 16);

    // Balanced distribution in units of 8-atom chunks (keeps the int4
    // key/species loads 16B-aligned: every warp start is a multiple of 8).
    const int  my_chunks  = chunks_base + (warp < chunks_rem);
    const long long start = 8LL * ((long long)warp * chunks_base +
                                   (warp < chunks_rem ? warp : chunks_rem));
    long long end = start + 8LL * my_chunks;
    if (end > n_atoms) end = (long long)n_atoms;
    if (start >= end) return;                    // uniform per warp

    const long long n      = end - start;
    const long long nbatch = n >> 3;             // batches of 8 atoms

    int   cur_key = -1;
    float acc0 = 0.0f, acc1 = 0.0f;

    // Flush the current segment for this half-warp (call half-converged).
    auto flush = [&]() {
        float t = acc0 + acc1;
        t += __shfl_xor_sync(halfmask, t, 8);
        t += __shfl_xor_sync(halfmask, t, 4);
        t += __shfl_xor_sync(halfmask, t, 2);
        t += __shfl_xor_sync(halfmask, t, 1);
        if (sub == 0 && cur_key >= 0)
            atomicAdd(out + cur_key, t);
    };
    // Process one atom with boundary check (slow path / tail).
    auto proc1 = [&](int k, int s, float4 x) {
        if (k != cur_key) {
            flush();
            cur_key = k; acc0 = 0.0f; acc1 = 0.0f;
        }
        const float4 w = Wsh[s * D_VEC4 + sub];
        acc0 = fmaf(x.x, w.x, acc0);
        acc1 = fmaf(x.y, w.y, acc1);
        acc0 = fmaf(x.z, w.z, acc0);
        acc1 = fmaf(x.w, w.w, acc1);
    };
    // One fully-loaded atom on the fast path.
    auto fma4 = [&](int s, const float4& x) {
        const float4 w = Wsh[s * D_VEC4 + sub];
        acc0 = fmaf(x.x, w.x, acc0);
        acc1 = fmaf(x.y, w.y, acc1);
        acc0 = fmaf(x.z, w.z, acc0);
        acc1 = fmaf(x.w, w.w, acc1);
    };

    // Hot-loop pointers (this half's first atom is start + half*4).
    const long long a0 = start + half * 4;
    const float4* xp = X4 + a0 * D_VEC4 + sub;
    const int*    kp = struct_idx + a0;
    const int*    sp = species + a0;

    for (long long b = 0; b < nbatch; ++b) {
        // Front-batched loads: 4 independent streaming float4s + vector keys.
        const float4 x0 = __ldcs(xp);
        const float4 x1 = __ldcs(xp + 1 * D_VEC4);
        const float4 x2 = __ldcs(xp + 2 * D_VEC4);
        const float4 x3 = __ldcs(xp + 3 * D_VEC4);
        const int4 kv = *reinterpret_cast<const int4*>(kp);
        const int4 sv = *reinterpret_cast<const int4*>(sp);
        xp += 8 * D_VEC4;   // 8 atoms forward (both halves)
        kp += 8;
        sp += 8;

        if (kv.x == cur_key && kv.w == cur_key) {
            // Sorted keys + first==last==cur -> all 4 atoms in current segment.
            fma4(sv.x, x0); fma4(sv.y, x1); fma4(sv.z, x2); fma4(sv.w, x3);
        } else {
            proc1(kv.x, sv.x, x0);
            proc1(kv.y, sv.y, x1);
            proc1(kv.z, sv.z, x2);
            proc1(kv.w, sv.w, x3);
        }
    }

    // Tail (< 8 atoms): 2 atoms per step, halves interleave; keys stay
    // monotone per half.
    for (long long a = start + nbatch * 8 + half; a < end; a += 2) {
        const int k = struct_idx[a];
        const int s = species[a];
        const float4 x = __ldcs(&X4[a * D_VEC4 + sub]);
        proc1(k, s, x);
    }

    // Final flush (all lanes converged here).
    flush();
}

extern "C" void kernel_launch(void* const* d_in, const int* in_sizes, int n_in,
                              void* d_out, int out_size)
{
    // Input order: X, W, central_species, structural_indices, n_structures
    const float* X  = (const float*)d_in[0];
    const float* W  = (const float*)d_in[1];
    const int*   sp = (const int*)  d_in[2];
    const int*   si = (const int*)  d_in[3];
    float* out = (float*)d_out;

    const int n_atoms = in_sizes[2];

    cudaMemsetAsync(d_out, 0, (size_t)out_size * sizeof(float), 0);

    // Oversubscribed grid: ~3.2 waves at 5 CTAs/SM residency (48-reg kernel).
    // Fine-grained chunks (~106 atoms/warp) smooth end-of-kernel imbalance.
    const int blocks = 2368;
    const int total_warps = blocks * WARPS_PER_BLOCK;   // 18944

    // Balanced distribution of 8-atom chunks across warps.
    const int total_chunks = (n_atoms + 7) >> 3;        // 250000 for 2M atoms
    const int chunks_base  = total_chunks / total_warps;
    const int chunks_rem   = total_chunks % total_warps;

    atomistic_kernel<<<blocks, THREADS_PER_BLOCK>>>(
        (const float4*)X, W, sp, si, out, n_atoms, chunks_base, chunks_rem);
}